// round 14
// baseline (speedup 1.0000x reference)
#include <cuda_runtime.h>
#include <math.h>

#define N_ATOMS 32769
#define N_BONDS 131073
#define ATOM_F 133
#define BOND_F 147
#define H      300
#define H3     900
#define MAXNB  6
#define NMOL   512
#define APM    64
#define H4     75      // H/4
#define H24    150     // 2H/4

// ---------------- scratch (device globals: allocation-free) ----------------
__device__ float g_input_atom[N_ATOMS * H];
__device__ float g_input_bond[N_BONDS * H];
__device__ float g_matom[N_ATOMS * H];
__device__ float g_mbond[N_BONDS * H];
__device__ float g_tmpb[N_BONDS * H];
__device__ float g_cat[N_ATOMS * H3];
__device__ float g_lr[N_ATOMS * H];
__device__ float g_msg[N_ATOMS * H];
__device__ float g_h0[NMOL * H];
__device__ float g_wt_ihf[H * H3];
__device__ float g_wt_hhf[H * H3];
__device__ float g_wt_ihb[H * H3];
__device__ float g_wt_hhb[H * H3];
__device__ float g_gif[(N_ATOMS - 1) * H3];
__device__ float g_gib[(N_ATOMS - 1) * H3];
__device__ float g_outf[APM * NMOL * H];
__device__ float g_outb[APM * NMOL * H];
__device__ float g_cat2[(N_ATOMS - 1) * 2 * H];
__device__ float g_ah[(N_ATOMS - 1) * H];

// ---------------- accurate transcendentals (R6 verbatim) ----------------
__device__ __forceinline__ float exp_acc(float x)
{
    x = fminf(fmaxf(x, -80.0f), 80.0f);
    const float L2E    = 1.4426950408889634f;
    const float L2E_HI = 1.442695021629333496f;
    const float L2E_LO = 1.9259629911266175e-8f;
    float r = rintf(x * L2E);
    float f = fmaf(x, L2E_HI, -r);
    f = fmaf(x, L2E_LO, f);
    float p = 1.5252733804e-5f;
    p = fmaf(p, f, 1.5435313916e-4f);
    p = fmaf(p, f, 1.3333558146e-3f);
    p = fmaf(p, f, 9.6181291076e-3f);
    p = fmaf(p, f, 5.5504108665e-2f);
    p = fmaf(p, f, 2.4022650696e-1f);
    p = fmaf(p, f, 6.9314718056e-1f);
    p = fmaf(p, f, 1.0f);
    float scale = __int_as_float(((int)r + 127) << 23);
    return p * scale;
}

__device__ __forceinline__ float sigm(float x)
{
    return __frcp_rn(1.0f + exp_acc(-x));
}

__device__ __forceinline__ float tanh_acc(float x)
{
    float ax = fabsf(x);
    float e = exp_acc(-2.0f * ax);
    float t = __fdiv_rn(1.0f - e, 1.0f + e);
    return copysignf(t, x);
}

// SACRED compensated MAC — R6 verbatim, plain ops. Under default ptxas -fmad
// fusion this compiles to the exact instruction stream that matches the
// reference (9.8e-5). DO NOT MODIFY in any way.
__device__ __forceinline__ void cmadd(float a, float b, float& acc, float& c)
{
    float p  = a * b;
    float pe = fmaf(a, b, -p);     // exact low part of the product
    float y  = p - c;
    float t  = acc + y;
    c = ((t - acc) - y) - pe;
    acc = t;
}

// ---------------- compensated fp32 GEMM: C = act(A@B (+addmat) (+bias)) ----------------
// BN=60: all N here are 300 or 900 (divisible by 60) — no padded-column
// compute. Per-output k-chain (cmadd sequence, BKK=16 zero-padding) is
// IDENTICAL to R6 — only the thread->output mapping changed.
#define BM 128
#define BN 60
#define BKK 16
__global__ void gemm_k(const float* __restrict__ A, const float* __restrict__ B,
                       float* __restrict__ C, int M, int N, int K,
                       const float* __restrict__ addmat, const float* __restrict__ bias,
                       int do_relu)
{
    __shared__ float As[BKK][BM];
    __shared__ float Bs[BKK][BN];
    int tx = threadIdx.x;           // 0..14 -> 4 columns each
    int ty = threadIdx.y;           // 0..15 -> 8 rows each
    int tid = ty * 15 + tx;         // 0..239
    int row0 = blockIdx.y * BM;
    int col0 = blockIdx.x * BN;

    float acc[8][4], cmp[8][4];
#pragma unroll
    for (int i = 0; i < 8; i++)
#pragma unroll
        for (int j = 0; j < 4; j++) { acc[i][j] = 0.f; cmp[i][j] = 0.f; }

    for (int k0 = 0; k0 < K; k0 += BKK) {
        // A tile: 128x16 (values/layout identical to R6; loader mapping only)
        for (int L = tid; L < BKK * BM; L += 240) {
            int m = L >> 4;
            int k = L & 15;
            int gr = row0 + m, gk = k0 + k;
            As[k][m] = (gr < M && gk < K) ? A[(size_t)gr * K + gk] : 0.f;
        }
        // B tile: 16x60
        for (int L = tid; L < BKK * BN; L += 240) {
            int k = L / BN;
            int n = L % BN;
            int gk = k0 + k, gc = col0 + n;
            Bs[k][n] = (gk < K && gc < N) ? B[(size_t)gk * N + gc] : 0.f;
        }
        __syncthreads();
#pragma unroll
        for (int kk = 0; kk < BKK; kk++) {
            float a[8], b[4];
#pragma unroll
            for (int i = 0; i < 8; i++) a[i] = As[kk][ty * 8 + i];
#pragma unroll
            for (int j = 0; j < 4; j++) b[j] = Bs[kk][tx * 4 + j];
#pragma unroll
            for (int i = 0; i < 8; i++)
#pragma unroll
                for (int j = 0; j < 4; j++) cmadd(a[i], b[j], acc[i][j], cmp[i][j]);
        }
        __syncthreads();
    }

#pragma unroll
    for (int i = 0; i < 8; i++) {
        int r = row0 + ty * 8 + i;
        if (r >= M) continue;
#pragma unroll
        for (int j = 0; j < 4; j++) {
            int c = col0 + tx * 4 + j;
            if (c >= N) continue;
            float v = acc[i][j] - cmp[i][j];   // fold compensation back in
            if (addmat) v += addmat[(size_t)r * N + c];
            if (bias) v += bias[c];
            if (do_relu) v = fmaxf(v, 0.f);
            C[(size_t)r * N + c] = v;
        }
    }
}

// ---------------- float4 elementwise/gather kernels (numerics-neutral) ----------------
__global__ void agg_update_k(const int* __restrict__ a2b, const float4* __restrict__ mb,
                             float4* __restrict__ matom)
{
    int idx = blockIdx.x * blockDim.x + threadIdx.x;
    if (idx >= N_ATOMS * H4) return;
    int i = idx / H4, c = idx % H4;
    float4 s = make_float4(0.f, 0.f, 0.f, 0.f);
    float4 mx = make_float4(-3.402823466e38f, -3.402823466e38f,
                            -3.402823466e38f, -3.402823466e38f);
#pragma unroll
    for (int j = 0; j < MAXNB; j++) {
        int e = a2b[i * MAXNB + j];
        float4 v = mb[(size_t)e * H4 + c];
        s.x += v.x; s.y += v.y; s.z += v.z; s.w += v.w;
        mx.x = fmaxf(mx.x, v.x); mx.y = fmaxf(mx.y, v.y);
        mx.z = fmaxf(mx.z, v.z); mx.w = fmaxf(mx.w, v.w);
    }
    float4 o = matom[idx];
    o.x += s.x * mx.x; o.y += s.y * mx.y; o.z += s.z * mx.z; o.w += s.w * mx.w;
    matom[idx] = o;
}

__global__ void bond_tmp_k(const int* __restrict__ b2a, const int* __restrict__ b2revb,
                           const float4* __restrict__ matom, const float4* __restrict__ mbond,
                           float4* __restrict__ tmp)
{
    int idx = blockIdx.x * blockDim.x + threadIdx.x;
    if (idx >= N_BONDS * H4) return;
    int e = idx / H4, c = idx % H4;
    float4 a = matom[(size_t)b2a[e] * H4 + c];
    float4 r = mbond[(size_t)b2revb[e] * H4 + c];
    tmp[idx] = make_float4(a.x - r.x, a.y - r.y, a.z - r.z, a.w - r.w);
}

__global__ void final_cat_k(const int* __restrict__ a2b, const float4* __restrict__ mb,
                            const float4* __restrict__ matom, const float4* __restrict__ inatom,
                            float4* __restrict__ cat)
{
    int idx = blockIdx.x * blockDim.x + threadIdx.x;
    if (idx >= N_ATOMS * H4) return;
    int i = idx / H4, c = idx % H4;
    float4 s = make_float4(0.f, 0.f, 0.f, 0.f);
    float4 mx = make_float4(-3.402823466e38f, -3.402823466e38f,
                            -3.402823466e38f, -3.402823466e38f);
#pragma unroll
    for (int j = 0; j < MAXNB; j++) {
        int e = a2b[i * MAXNB + j];
        float4 v = mb[(size_t)e * H4 + c];
        s.x += v.x; s.y += v.y; s.z += v.z; s.w += v.w;
        mx.x = fmaxf(mx.x, v.x); mx.y = fmaxf(mx.y, v.y);
        mx.z = fmaxf(mx.z, v.z); mx.w = fmaxf(mx.w, v.w);
    }
    cat[(size_t)i * (3 * H4) + c] =
        make_float4(s.x * mx.x, s.y * mx.y, s.z * mx.z, s.w * mx.w);
    cat[(size_t)i * (3 * H4) + H4 + c] = matom[idx];
    cat[(size_t)i * (3 * H4) + 2 * H4 + c] = inatom[idx];
}

__global__ void msg_k(const float4* __restrict__ lr, const float4* __restrict__ gbias,
                      float4* __restrict__ msg)
{
    int idx = blockIdx.x * blockDim.x + threadIdx.x;
    if (idx >= N_ATOMS * H4) return;
    int c = idx % H4;
    float4 v = lr[idx], b = gbias[c];
    msg[idx] = make_float4(fmaxf(v.x + b.x, 0.f), fmaxf(v.y + b.y, 0.f),
                           fmaxf(v.z + b.z, 0.f), fmaxf(v.w + b.w, 0.f));
}

__global__ void h0_k(const float* __restrict__ lr, float* __restrict__ h0)
{
    int idx = blockIdx.x * blockDim.x + threadIdx.x;
    if (idx >= NMOL * H) return;
    int b = idx / H, c = idx % H;
    float m = -3.402823466e38f;
    for (int t = 0; t < APM; t++)
        m = fmaxf(m, lr[(size_t)(1 + b * APM + t) * H + c]);
    h0[idx] = m;
}

// W: [H3, H] -> WT: [H, H3] (exact fp32)
__global__ void transpose_k(const float* __restrict__ W, float* __restrict__ WT)
{
    int idx = blockIdx.x * blockDim.x + threadIdx.x;
    if (idx >= H3 * H) return;
    int j = idx / H, k = idx % H;
    WT[(size_t)k * H3 + j] = W[idx];
}

// ---------------- fused bidirectional GRU step (R6 VERBATIM) ----------------
__global__ void gru_step_k(int s,
                           const float* __restrict__ gi_f, const float* __restrict__ gi_b,
                           const float* __restrict__ WTf, const float* __restrict__ WTb,
                           const float* __restrict__ bhhf, const float* __restrict__ bhhb,
                           const float* __restrict__ h0,
                           float* __restrict__ outf, float* __restrict__ outb)
{
    int dir = blockIdx.y;
    int b0 = blockIdx.x * 8;
    int c = threadIdx.x;  // 0..H-1

    const float* gi = dir ? gi_b : gi_f;
    const float* W = dir ? WTb : WTf;
    const float* bh = dir ? bhhb : bhhf;
    float* outbuf = dir ? outb : outf;
    int t = dir ? (APM - 1 - s) : s;
    const float* hprev = (s == 0) ? h0
                                  : (outbuf + (size_t)(dir ? (t + 1) : (t - 1)) * NMOL * H);

    __shared__ float hs[8][H];
#pragma unroll
    for (int bb = 0; bb < 8; bb++)
        hs[bb][c] = hprev[(size_t)(b0 + bb) * H + c];
    __syncthreads();

    float r0[8], r1[8], r2[8];
    float c0[8], c1[8], c2[8];
#pragma unroll
    for (int bb = 0; bb < 8; bb++) {
        r0[bb] = 0.f; r1[bb] = 0.f; r2[bb] = 0.f;
        c0[bb] = 0.f; c1[bb] = 0.f; c2[bb] = 0.f;
    }

    for (int k = 0; k < H; k++) {
        float w0 = W[(size_t)k * H3 + c];
        float w1 = W[(size_t)k * H3 + H + c];
        float w2 = W[(size_t)k * H3 + 2 * H + c];
#pragma unroll
        for (int bb = 0; bb < 8; bb++) {
            float h = hs[bb][k];
            cmadd(w0, h, r0[bb], c0[bb]);
            cmadd(w1, h, r1[bb], c1[bb]);
            cmadd(w2, h, r2[bb], c2[bb]);
        }
    }

#pragma unroll
    for (int bb = 0; bb < 8; bb++) {
        int b = b0 + bb;
        size_t gidx = (size_t)(b * APM + t) * H3 + c;
        float g0 = r0[bb] - c0[bb];
        float g1 = r1[bb] - c1[bb];
        float g2 = r2[bb] - c2[bb];
        float r = sigm(gi[gidx] + g0 + bh[c]);
        float z = sigm(gi[gidx + H] + g1 + bh[H + c]);
        float n = tanh_acc(gi[gidx + 2 * H] + r * (g2 + bh[2 * H + c]));
        float hv = hs[bb][c];
        outbuf[(size_t)t * NMOL * H + (size_t)b * H + c] = (1.f - z) * n + z * hv;
    }
}

__global__ void gru_cat_k(const float4* __restrict__ outf, const float4* __restrict__ outb,
                          float4* __restrict__ cat2)
{
    int idx = blockIdx.x * blockDim.x + threadIdx.x;
    if (idx >= (N_ATOMS - 1) * H24) return;
    int m = idx / H24, c = idx % H24;
    int b = m / APM, t = m % APM;
    cat2[idx] = (c < H4) ? outf[(size_t)t * NMOL * H4 + (size_t)b * H4 + c]
                         : outb[(size_t)t * NMOL * H4 + (size_t)b * H4 + (c - H4)];
}

__global__ void mean_k(const float* __restrict__ ah, float* __restrict__ out)
{
    int idx = blockIdx.x * blockDim.x + threadIdx.x;
    if (idx >= NMOL * H) return;
    int b = idx / H, c = idx % H;
    float s = 0.f, comp = 0.f;
    for (int t = 0; t < APM; t++) {
        float v = ah[(size_t)(b * APM + t) * H + c];
        float y = v - comp;
        float u = s + y;
        comp = (u - s) - y;
        s = u;
    }
    out[idx] = s * (1.0f / APM);
}

// ---------------- launch ----------------
extern "C" void kernel_launch(void* const* d_in, const int* in_sizes, int n_in,
                              void* d_out, int out_size)
{
    const float* f_atoms  = (const float*)d_in[0];
    const float* f_bonds  = (const float*)d_in[1];
    const float* W_i_atom = (const float*)d_in[2];
    const float* W_i_bond = (const float*)d_in[3];
    const float* W_h_0    = (const float*)d_in[4];
    const float* W_h_1    = (const float*)d_in[5];
    const float* W_lr     = (const float*)d_in[6];
    const float* W_o      = (const float*)d_in[7];
    const float* b_o      = (const float*)d_in[8];
    const float* gru_bias = (const float*)d_in[9];
    const float* Wih_f    = (const float*)d_in[10];
    const float* Whh_f    = (const float*)d_in[11];
    const float* bih_f    = (const float*)d_in[12];
    const float* bhh_f    = (const float*)d_in[13];
    const float* Wih_b    = (const float*)d_in[14];
    const float* Whh_b    = (const float*)d_in[15];
    const float* bih_b    = (const float*)d_in[16];
    const float* bhh_b    = (const float*)d_in[17];
    const int* a2b    = (const int*)d_in[18];
    const int* b2a    = (const int*)d_in[19];
    const int* b2revb = (const int*)d_in[20];
    float* out = (float*)d_out;

    float *p_ia, *p_ib, *p_ma, *p_mb, *p_tmp, *p_cat, *p_lr, *p_msg, *p_h0;
    float *p_wtihf, *p_wthhf, *p_wtihb, *p_wthhb, *p_gif, *p_gib;
    float *p_outf, *p_outb, *p_cat2, *p_ah;
    cudaGetSymbolAddress((void**)&p_ia, g_input_atom);
    cudaGetSymbolAddress((void**)&p_ib, g_input_bond);
    cudaGetSymbolAddress((void**)&p_ma, g_matom);
    cudaGetSymbolAddress((void**)&p_mb, g_mbond);
    cudaGetSymbolAddress((void**)&p_tmp, g_tmpb);
    cudaGetSymbolAddress((void**)&p_cat, g_cat);
    cudaGetSymbolAddress((void**)&p_lr, g_lr);
    cudaGetSymbolAddress((void**)&p_msg, g_msg);
    cudaGetSymbolAddress((void**)&p_h0, g_h0);
    cudaGetSymbolAddress((void**)&p_wtihf, g_wt_ihf);
    cudaGetSymbolAddress((void**)&p_wthhf, g_wt_hhf);
    cudaGetSymbolAddress((void**)&p_wtihb, g_wt_ihb);
    cudaGetSymbolAddress((void**)&p_wthhb, g_wt_hhb);
    cudaGetSymbolAddress((void**)&p_gif, g_gif);
    cudaGetSymbolAddress((void**)&p_gib, g_gib);
    cudaGetSymbolAddress((void**)&p_outf, g_outf);
    cudaGetSymbolAddress((void**)&p_outb, g_outb);
    cudaGetSymbolAddress((void**)&p_cat2, g_cat2);
    cudaGetSymbolAddress((void**)&p_ah, g_ah);

    dim3 gthr(15, 16);
    auto gemm_grid = [](int M, int N) { return dim3((N + BN - 1) / BN, (M + BM - 1) / BM); };
    const int EB = 256;

    // 1) input projections
    gemm_k<<<gemm_grid(N_ATOMS, H), gthr>>>(f_atoms, W_i_atom, p_ia, N_ATOMS, H, ATOM_F,
                                            nullptr, nullptr, 1);
    gemm_k<<<gemm_grid(N_BONDS, H), gthr>>>(f_bonds, W_i_bond, p_ib, N_BONDS, H, BOND_F,
                                            nullptr, nullptr, 1);
    cudaMemcpyAsync(p_ma, p_ia, sizeof(float) * (size_t)N_ATOMS * H, cudaMemcpyDeviceToDevice, 0);
    cudaMemcpyAsync(p_mb, p_ib, sizeof(float) * (size_t)N_BONDS * H, cudaMemcpyDeviceToDevice, 0);

    // 2) two message-passing steps
    for (int d = 0; d < 2; d++) {
        agg_update_k<<<(N_ATOMS * H4 + EB - 1) / EB, EB>>>(a2b, (const float4*)p_mb,
                                                           (float4*)p_ma);
        bond_tmp_k<<<(N_BONDS * H4 + EB - 1) / EB, EB>>>(b2a, b2revb, (const float4*)p_ma,
                                                         (const float4*)p_mb, (float4*)p_tmp);
        gemm_k<<<gemm_grid(N_BONDS, H), gthr>>>(p_tmp, d ? W_h_1 : W_h_0, p_mb,
                                                N_BONDS, H, H, p_ib, nullptr, 1);
    }

    // 3) final aggregation + concat + readout
    final_cat_k<<<(N_ATOMS * H4 + EB - 1) / EB, EB>>>(a2b, (const float4*)p_mb,
                                                      (const float4*)p_ma, (const float4*)p_ia,
                                                      (float4*)p_cat);
    gemm_k<<<gemm_grid(N_ATOMS, H), gthr>>>(p_cat, W_lr, p_lr, N_ATOMS, H, H3,
                                            nullptr, nullptr, 0);

    // 4) GRU prep
    msg_k<<<(N_ATOMS * H4 + EB - 1) / EB, EB>>>((const float4*)p_lr, (const float4*)gru_bias,
                                                (float4*)p_msg);
    h0_k<<<(NMOL * H + EB - 1) / EB, EB>>>(p_lr, p_h0);
    transpose_k<<<(H3 * H + EB - 1) / EB, EB>>>(Wih_f, p_wtihf);
    transpose_k<<<(H3 * H + EB - 1) / EB, EB>>>(Whh_f, p_wthhf);
    transpose_k<<<(H3 * H + EB - 1) / EB, EB>>>(Wih_b, p_wtihb);
    transpose_k<<<(H3 * H + EB - 1) / EB, EB>>>(Whh_b, p_wthhb);

    // gi = x @ Wih^T + bih for all timesteps
    gemm_k<<<gemm_grid(NMOL * APM, H3), gthr>>>(p_msg + H, p_wtihf, p_gif,
                                                NMOL * APM, H3, H, nullptr, bih_f, 0);
    gemm_k<<<gemm_grid(NMOL * APM, H3), gthr>>>(p_msg + H, p_wtihb, p_gib,
                                                NMOL * APM, H3, H, nullptr, bih_b, 0);

    // 5) 64 fused bidirectional GRU steps
    for (int s = 0; s < APM; s++)
        gru_step_k<<<dim3(NMOL / 8, 2), H>>>(s, p_gif, p_gib, p_wthhf, p_wthhb,
                                             bhh_f, bhh_b, p_h0, p_outf, p_outb);

    // 6) concat directions, output projection, per-molecule mean
    gru_cat_k<<<((N_ATOMS - 1) * H24 + EB - 1) / EB, EB>>>((const float4*)p_outf,
                                                           (const float4*)p_outb,
                                                           (float4*)p_cat2);
    gemm_k<<<gemm_grid(NMOL * APM, H), gthr>>>(p_cat2, W_o, p_ah,
                                               NMOL * APM, H, 2 * H, nullptr, b_o, 1);
    mean_k<<<(NMOL * H + EB - 1) / EB, EB>>>(p_ah, out);
}

// round 15
// speedup vs baseline: 1.2805x; 1.2805x over previous
#include <cuda_runtime.h>
#include <math.h>

#define N_ATOMS 32769
#define N_BONDS 131073
#define ATOM_F 133
#define BOND_F 147
#define H      300
#define H3     900
#define MAXNB  6
#define NMOL   512
#define APM    64
#define H4     75      // H/4
#define H24    150     // 2H/4

// ---------------- scratch (device globals: allocation-free) ----------------
__device__ float g_input_atom[N_ATOMS * H];
__device__ float g_input_bond[N_BONDS * H];
__device__ float g_matom[N_ATOMS * H];
__device__ float g_mbond[N_BONDS * H];
__device__ float g_tmpb[N_BONDS * H];
__device__ float g_cat[N_ATOMS * H3];
__device__ float g_lr[N_ATOMS * H];
__device__ float g_msg[N_ATOMS * H];
__device__ float g_h0[NMOL * H];
__device__ float g_wt_ihf[H * H3];
__device__ float g_wt_hhf[H * H3];
__device__ float g_wt_ihb[H * H3];
__device__ float g_wt_hhb[H * H3];
__device__ float g_gif[(N_ATOMS - 1) * H3];
__device__ float g_gib[(N_ATOMS - 1) * H3];
__device__ float g_outf[APM * NMOL * H];
__device__ float g_outb[APM * NMOL * H];
__device__ float g_cat2[(N_ATOMS - 1) * 2 * H];
__device__ float g_ah[(N_ATOMS - 1) * H];

typedef unsigned long long u64;
#define SGN2 0x8000000080000000ULL

// ---------------- packed f32x2 primitives (R10 verbatim, proven) ----------------
__device__ __forceinline__ u64 pk(float lo, float hi)
{
    u64 d;
    asm("mov.b64 %0, {%1, %2};" : "=l"(d) : "f"(lo), "f"(hi));
    return d;
}
__device__ __forceinline__ void upk(u64 v, float& lo, float& hi)
{
    asm("mov.b64 {%0, %1}, %2;" : "=f"(lo), "=f"(hi) : "l"(v));
}
__device__ __forceinline__ u64 pmul(u64 a, u64 b)
{
    u64 d;
    asm("mul.rn.f32x2 %0, %1, %2;" : "=l"(d) : "l"(a), "l"(b));
    return d;
}
__device__ __forceinline__ u64 padd(u64 a, u64 b)
{
    u64 d;
    asm("add.rn.f32x2 %0, %1, %2;" : "=l"(d) : "l"(a), "l"(b));
    return d;
}
__device__ __forceinline__ u64 pfma(u64 a, u64 b, u64 c)
{
    u64 d;
    asm("fma.rn.f32x2 %0, %1, %2, %3;" : "=l"(d) : "l"(a), "l"(b), "l"(c));
    return d;
}

// Packed compensated MAC — R10 verbatim (bitwise-matches R6's sacred cmadd).
__device__ __forceinline__ void pcmadd(u64 A, u64 B, u64& ACC, u64& CN)
{
    u64 P  = pmul(A, B);
    u64 PE = pfma(A, B, P ^ SGN2);      // exact low part of the products
    u64 Y  = padd(P, CN);               // p - c
    u64 T  = padd(ACC, Y);
    u64 U  = padd(ACC, T ^ SGN2);       // acc - t
    u64 V  = padd(U, Y);                // -( (t-acc) - y )
    CN  = padd(V, PE);                  // -( ((t-acc)-y) - pe )
    ACC = T;
}

// ---------------- accurate transcendentals (R6 verbatim) ----------------
__device__ __forceinline__ float exp_acc(float x)
{
    x = fminf(fmaxf(x, -80.0f), 80.0f);
    const float L2E    = 1.4426950408889634f;
    const float L2E_HI = 1.442695021629333496f;
    const float L2E_LO = 1.9259629911266175e-8f;
    float r = rintf(x * L2E);
    float f = fmaf(x, L2E_HI, -r);
    f = fmaf(x, L2E_LO, f);
    float p = 1.5252733804e-5f;
    p = fmaf(p, f, 1.5435313916e-4f);
    p = fmaf(p, f, 1.3333558146e-3f);
    p = fmaf(p, f, 9.6181291076e-3f);
    p = fmaf(p, f, 5.5504108665e-2f);
    p = fmaf(p, f, 2.4022650696e-1f);
    p = fmaf(p, f, 6.9314718056e-1f);
    p = fmaf(p, f, 1.0f);
    float scale = __int_as_float(((int)r + 127) << 23);
    return p * scale;
}

__device__ __forceinline__ float sigm(float x)
{
    return __frcp_rn(1.0f + exp_acc(-x));
}

__device__ __forceinline__ float tanh_acc(float x)
{
    float ax = fabsf(x);
    float e = exp_acc(-2.0f * ax);
    float t = __fdiv_rn(1.0f - e, 1.0f + e);
    return copysignf(t, x);
}

// SACRED compensated MAC — R6 verbatim. DO NOT MODIFY.
__device__ __forceinline__ void cmadd(float a, float b, float& acc, float& c)
{
    float p  = a * b;
    float pe = fmaf(a, b, -p);     // exact low part of the product
    float y  = p - c;
    float t  = acc + y;
    c = ((t - acc) - y) - pe;
    acc = t;
}

// ---------------- packed compensated fp32 GEMM (R10 verbatim) ----------------
#define BM 128
#define BN 64
#define BKK 16
__global__ void gemm_k(const float* __restrict__ A, const float* __restrict__ B,
                       float* __restrict__ C, int M, int N, int K,
                       const float* __restrict__ addmat, const float* __restrict__ bias,
                       int do_relu)
{
    __shared__ float As[BKK][BM];
    __shared__ float Bs[BKK][BN];
    int tx = threadIdx.x;           // 0..15 -> 4 columns = 2 packed pairs
    int ty = threadIdx.y;           // 0..15 -> 8 rows
    int tid = ty * 16 + tx;
    int row0 = blockIdx.y * BM;
    int col0 = blockIdx.x * BN;

    u64 acc[8][2], cn[8][2];
#pragma unroll
    for (int i = 0; i < 8; i++)
#pragma unroll
        for (int j = 0; j < 2; j++) { acc[i][j] = 0ULL; cn[i][j] = 0ULL; }

    for (int k0 = 0; k0 < K; k0 += BKK) {
#pragma unroll
        for (int i = 0; i < 8; i++) {
            int L = tid * 8 + i;
            int m = L >> 4;
            int k = L & 15;
            int gr = row0 + m, gk = k0 + k;
            As[k][m] = (gr < M && gk < K) ? A[(size_t)gr * K + gk] : 0.f;
        }
#pragma unroll
        for (int i = 0; i < 4; i++) {
            int L = tid * 4 + i;
            int k = L >> 6;
            int n = L & 63;
            int gk = k0 + k, gc = col0 + n;
            Bs[k][n] = (gk < K && gc < N) ? B[(size_t)gk * N + gc] : 0.f;
        }
        __syncthreads();
#pragma unroll
        for (int kk = 0; kk < BKK; kk++) {
            u64 pb0 = *reinterpret_cast<const u64*>(&Bs[kk][tx * 4]);
            u64 pb1 = *reinterpret_cast<const u64*>(&Bs[kk][tx * 4 + 2]);
#pragma unroll
            for (int i = 0; i < 8; i++) {
                float a = As[kk][ty * 8 + i];
                u64 pa = pk(a, a);
                pcmadd(pa, pb0, acc[i][0], cn[i][0]);
                pcmadd(pa, pb1, acc[i][1], cn[i][1]);
            }
        }
        __syncthreads();
    }

#pragma unroll
    for (int i = 0; i < 8; i++) {
        int r = row0 + ty * 8 + i;
        if (r >= M) continue;
#pragma unroll
        for (int j = 0; j < 2; j++) {
            float v0, v1;
            upk(padd(acc[i][j], cn[i][j]), v0, v1);   // acc - c (cn negated)
            float vv[2] = { v0, v1 };
#pragma unroll
            for (int q = 0; q < 2; q++) {
                int c = col0 + tx * 4 + j * 2 + q;
                if (c >= N) continue;
                float v = vv[q];
                if (addmat) v += addmat[(size_t)r * N + c];
                if (bias) v += bias[c];
                if (do_relu) v = fmaxf(v, 0.f);
                C[(size_t)r * N + c] = v;
            }
        }
    }
}

// ---------------- plain-FMA GEMM (post-GRU only: amplification ~= 1) ----------------
// Used ONLY for the W_o output projection; its ~1e-6 ordering noise reaches
// the output unamplified.
__global__ void gemm_plain_k(const float* __restrict__ A, const float* __restrict__ B,
                             float* __restrict__ C, int M, int N, int K,
                             const float* __restrict__ bias, int do_relu)
{
    __shared__ float As[BKK][BM];
    __shared__ float Bs[BKK][BN];
    int tx = threadIdx.x;
    int ty = threadIdx.y;
    int tid = ty * 16 + tx;
    int row0 = blockIdx.y * BM;
    int col0 = blockIdx.x * BN;

    float acc[8][4];
#pragma unroll
    for (int i = 0; i < 8; i++)
#pragma unroll
        for (int j = 0; j < 4; j++) acc[i][j] = 0.f;

    for (int k0 = 0; k0 < K; k0 += BKK) {
#pragma unroll
        for (int i = 0; i < 8; i++) {
            int L = tid * 8 + i;
            int m = L >> 4;
            int k = L & 15;
            int gr = row0 + m, gk = k0 + k;
            As[k][m] = (gr < M && gk < K) ? A[(size_t)gr * K + gk] : 0.f;
        }
#pragma unroll
        for (int i = 0; i < 4; i++) {
            int L = tid * 4 + i;
            int k = L >> 6;
            int n = L & 63;
            int gk = k0 + k, gc = col0 + n;
            Bs[k][n] = (gk < K && gc < N) ? B[(size_t)gk * N + gc] : 0.f;
        }
        __syncthreads();
#pragma unroll
        for (int kk = 0; kk < BKK; kk++) {
            float a[8], b[4];
#pragma unroll
            for (int i = 0; i < 8; i++) a[i] = As[kk][ty * 8 + i];
#pragma unroll
            for (int j = 0; j < 4; j++) b[j] = Bs[kk][tx * 4 + j];
#pragma unroll
            for (int i = 0; i < 8; i++)
#pragma unroll
                for (int j = 0; j < 4; j++)
                    acc[i][j] = __fmaf_rn(a[i], b[j], acc[i][j]);
        }
        __syncthreads();
    }

#pragma unroll
    for (int i = 0; i < 8; i++) {
        int r = row0 + ty * 8 + i;
        if (r >= M) continue;
#pragma unroll
        for (int j = 0; j < 4; j++) {
            int c = col0 + tx * 4 + j;
            if (c >= N) continue;
            float v = acc[i][j];
            if (bias) v += bias[c];
            if (do_relu) v = fmaxf(v, 0.f);
            C[(size_t)r * N + c] = v;
        }
    }
}

// ---------------- float4 elementwise/gather kernels (R14 verbatim, proven) ----------------
__global__ void agg_update_k(const int* __restrict__ a2b, const float4* __restrict__ mb,
                             float4* __restrict__ matom)
{
    int idx = blockIdx.x * blockDim.x + threadIdx.x;
    if (idx >= N_ATOMS * H4) return;
    int i = idx / H4, c = idx % H4;
    float4 s = make_float4(0.f, 0.f, 0.f, 0.f);
    float4 mx = make_float4(-3.402823466e38f, -3.402823466e38f,
                            -3.402823466e38f, -3.402823466e38f);
#pragma unroll
    for (int j = 0; j < MAXNB; j++) {
        int e = a2b[i * MAXNB + j];
        float4 v = mb[(size_t)e * H4 + c];
        s.x += v.x; s.y += v.y; s.z += v.z; s.w += v.w;
        mx.x = fmaxf(mx.x, v.x); mx.y = fmaxf(mx.y, v.y);
        mx.z = fmaxf(mx.z, v.z); mx.w = fmaxf(mx.w, v.w);
    }
    float4 o = matom[idx];
    o.x += s.x * mx.x; o.y += s.y * mx.y; o.z += s.z * mx.z; o.w += s.w * mx.w;
    matom[idx] = o;
}

__global__ void bond_tmp_k(const int* __restrict__ b2a, const int* __restrict__ b2revb,
                           const float4* __restrict__ matom, const float4* __restrict__ mbond,
                           float4* __restrict__ tmp)
{
    int idx = blockIdx.x * blockDim.x + threadIdx.x;
    if (idx >= N_BONDS * H4) return;
    int e = idx / H4, c = idx % H4;
    float4 a = matom[(size_t)b2a[e] * H4 + c];
    float4 r = mbond[(size_t)b2revb[e] * H4 + c];
    tmp[idx] = make_float4(a.x - r.x, a.y - r.y, a.z - r.z, a.w - r.w);
}

__global__ void final_cat_k(const int* __restrict__ a2b, const float4* __restrict__ mb,
                            const float4* __restrict__ matom, const float4* __restrict__ inatom,
                            float4* __restrict__ cat)
{
    int idx = blockIdx.x * blockDim.x + threadIdx.x;
    if (idx >= N_ATOMS * H4) return;
    int i = idx / H4, c = idx % H4;
    float4 s = make_float4(0.f, 0.f, 0.f, 0.f);
    float4 mx = make_float4(-3.402823466e38f, -3.402823466e38f,
                            -3.402823466e38f, -3.402823466e38f);
#pragma unroll
    for (int j = 0; j < MAXNB; j++) {
        int e = a2b[i * MAXNB + j];
        float4 v = mb[(size_t)e * H4 + c];
        s.x += v.x; s.y += v.y; s.z += v.z; s.w += v.w;
        mx.x = fmaxf(mx.x, v.x); mx.y = fmaxf(mx.y, v.y);
        mx.z = fmaxf(mx.z, v.z); mx.w = fmaxf(mx.w, v.w);
    }
    cat[(size_t)i * (3 * H4) + c] =
        make_float4(s.x * mx.x, s.y * mx.y, s.z * mx.z, s.w * mx.w);
    cat[(size_t)i * (3 * H4) + H4 + c] = matom[idx];
    cat[(size_t)i * (3 * H4) + 2 * H4 + c] = inatom[idx];
}

__global__ void msg_k(const float4* __restrict__ lr, const float4* __restrict__ gbias,
                      float4* __restrict__ msg)
{
    int idx = blockIdx.x * blockDim.x + threadIdx.x;
    if (idx >= N_ATOMS * H4) return;
    int c = idx % H4;
    float4 v = lr[idx], b = gbias[c];
    msg[idx] = make_float4(fmaxf(v.x + b.x, 0.f), fmaxf(v.y + b.y, 0.f),
                           fmaxf(v.z + b.z, 0.f), fmaxf(v.w + b.w, 0.f));
}

__global__ void h0_k(const float* __restrict__ lr, float* __restrict__ h0)
{
    int idx = blockIdx.x * blockDim.x + threadIdx.x;
    if (idx >= NMOL * H) return;
    int b = idx / H, c = idx % H;
    float m = -3.402823466e38f;
    for (int t = 0; t < APM; t++)
        m = fmaxf(m, lr[(size_t)(1 + b * APM + t) * H + c]);
    h0[idx] = m;
}

// W: [H3, H] -> WT: [H, H3] (exact fp32)
__global__ void transpose_k(const float* __restrict__ W, float* __restrict__ WT)
{
    int idx = blockIdx.x * blockDim.x + threadIdx.x;
    if (idx >= H3 * H) return;
    int j = idx / H, k = idx % H;
    WT[(size_t)k * H3 + j] = W[idx];
}

// ---------------- fused bidirectional GRU step (R6 arithmetic, 4 mols/block) ----------------
// Per-output cmadd chain identical to R6 (bitwise); only block geometry changed
// so all 148 SMs get work (256 blocks vs 128).
__global__ void gru_step_k(int s,
                           const float* __restrict__ gi_f, const float* __restrict__ gi_b,
                           const float* __restrict__ WTf, const float* __restrict__ WTb,
                           const float* __restrict__ bhhf, const float* __restrict__ bhhb,
                           const float* __restrict__ h0,
                           float* __restrict__ outf, float* __restrict__ outb)
{
    int dir = blockIdx.y;
    int b0 = blockIdx.x * 4;
    int c = threadIdx.x;  // 0..H-1

    const float* gi = dir ? gi_b : gi_f;
    const float* W = dir ? WTb : WTf;
    const float* bh = dir ? bhhb : bhhf;
    float* outbuf = dir ? outb : outf;
    int t = dir ? (APM - 1 - s) : s;
    const float* hprev = (s == 0) ? h0
                                  : (outbuf + (size_t)(dir ? (t + 1) : (t - 1)) * NMOL * H);

    __shared__ float hs[4][H];
#pragma unroll
    for (int bb = 0; bb < 4; bb++)
        hs[bb][c] = hprev[(size_t)(b0 + bb) * H + c];
    __syncthreads();

    float r0[4], r1[4], r2[4];
    float c0[4], c1[4], c2[4];
#pragma unroll
    for (int bb = 0; bb < 4; bb++) {
        r0[bb] = 0.f; r1[bb] = 0.f; r2[bb] = 0.f;
        c0[bb] = 0.f; c1[bb] = 0.f; c2[bb] = 0.f;
    }

    for (int k = 0; k < H; k++) {
        float w0 = W[(size_t)k * H3 + c];
        float w1 = W[(size_t)k * H3 + H + c];
        float w2 = W[(size_t)k * H3 + 2 * H + c];
#pragma unroll
        for (int bb = 0; bb < 4; bb++) {
            float h = hs[bb][k];
            cmadd(w0, h, r0[bb], c0[bb]);
            cmadd(w1, h, r1[bb], c1[bb]);
            cmadd(w2, h, r2[bb], c2[bb]);
        }
    }

#pragma unroll
    for (int bb = 0; bb < 4; bb++) {
        int b = b0 + bb;
        size_t gidx = (size_t)(b * APM + t) * H3 + c;
        float g0 = r0[bb] - c0[bb];
        float g1 = r1[bb] - c1[bb];
        float g2 = r2[bb] - c2[bb];
        float r = sigm(gi[gidx] + g0 + bh[c]);
        float z = sigm(gi[gidx + H] + g1 + bh[H + c]);
        float n = tanh_acc(gi[gidx + 2 * H] + r * (g2 + bh[2 * H + c]));
        float hv = hs[bb][c];
        outbuf[(size_t)t * NMOL * H + (size_t)b * H + c] = (1.f - z) * n + z * hv;
    }
}

__global__ void gru_cat_k(const float4* __restrict__ outf, const float4* __restrict__ outb,
                          float4* __restrict__ cat2)
{
    int idx = blockIdx.x * blockDim.x + threadIdx.x;
    if (idx >= (N_ATOMS - 1) * H24) return;
    int m = idx / H24, c = idx % H24;
    int b = m / APM, t = m % APM;
    cat2[idx] = (c < H4) ? outf[(size_t)t * NMOL * H4 + (size_t)b * H4 + c]
                         : outb[(size_t)t * NMOL * H4 + (size_t)b * H4 + (c - H4)];
}

__global__ void mean_k(const float* __restrict__ ah, float* __restrict__ out)
{
    int idx = blockIdx.x * blockDim.x + threadIdx.x;
    if (idx >= NMOL * H) return;
    int b = idx / H, c = idx % H;
    float s = 0.f, comp = 0.f;
    for (int t = 0; t < APM; t++) {
        float v = ah[(size_t)(b * APM + t) * H + c];
        float y = v - comp;
        float u = s + y;
        comp = (u - s) - y;
        s = u;
    }
    out[idx] = s * (1.0f / APM);
}

// ---------------- launch ----------------
extern "C" void kernel_launch(void* const* d_in, const int* in_sizes, int n_in,
                              void* d_out, int out_size)
{
    const float* f_atoms  = (const float*)d_in[0];
    const float* f_bonds  = (const float*)d_in[1];
    const float* W_i_atom = (const float*)d_in[2];
    const float* W_i_bond = (const float*)d_in[3];
    const float* W_h_0    = (const float*)d_in[4];
    const float* W_h_1    = (const float*)d_in[5];
    const float* W_lr     = (const float*)d_in[6];
    const float* W_o      = (const float*)d_in[7];
    const float* b_o      = (const float*)d_in[8];
    const float* gru_bias = (const float*)d_in[9];
    const float* Wih_f    = (const float*)d_in[10];
    const float* Whh_f    = (const float*)d_in[11];
    const float* bih_f    = (const float*)d_in[12];
    const float* bhh_f    = (const float*)d_in[13];
    const float* Wih_b    = (const float*)d_in[14];
    const float* Whh_b    = (const float*)d_in[15];
    const float* bih_b    = (const float*)d_in[16];
    const float* bhh_b    = (const float*)d_in[17];
    const int* a2b    = (const int*)d_in[18];
    const int* b2a    = (const int*)d_in[19];
    const int* b2revb = (const int*)d_in[20];
    float* out = (float*)d_out;

    float *p_ia, *p_ib, *p_ma, *p_mb, *p_tmp, *p_cat, *p_lr, *p_msg, *p_h0;
    float *p_wtihf, *p_wthhf, *p_wtihb, *p_wthhb, *p_gif, *p_gib;
    float *p_outf, *p_outb, *p_cat2, *p_ah;
    cudaGetSymbolAddress((void**)&p_ia, g_input_atom);
    cudaGetSymbolAddress((void**)&p_ib, g_input_bond);
    cudaGetSymbolAddress((void**)&p_ma, g_matom);
    cudaGetSymbolAddress((void**)&p_mb, g_mbond);
    cudaGetSymbolAddress((void**)&p_tmp, g_tmpb);
    cudaGetSymbolAddress((void**)&p_cat, g_cat);
    cudaGetSymbolAddress((void**)&p_lr, g_lr);
    cudaGetSymbolAddress((void**)&p_msg, g_msg);
    cudaGetSymbolAddress((void**)&p_h0, g_h0);
    cudaGetSymbolAddress((void**)&p_wtihf, g_wt_ihf);
    cudaGetSymbolAddress((void**)&p_wthhf, g_wt_hhf);
    cudaGetSymbolAddress((void**)&p_wtihb, g_wt_ihb);
    cudaGetSymbolAddress((void**)&p_wthhb, g_wt_hhb);
    cudaGetSymbolAddress((void**)&p_gif, g_gif);
    cudaGetSymbolAddress((void**)&p_gib, g_gib);
    cudaGetSymbolAddress((void**)&p_outf, g_outf);
    cudaGetSymbolAddress((void**)&p_outb, g_outb);
    cudaGetSymbolAddress((void**)&p_cat2, g_cat2);
    cudaGetSymbolAddress((void**)&p_ah, g_ah);

    dim3 gthr(16, 16);
    auto gemm_grid = [](int M, int N) { return dim3((N + BN - 1) / BN, (M + BM - 1) / BM); };
    const int EB = 256;

    // 1) input projections
    gemm_k<<<gemm_grid(N_ATOMS, H), gthr>>>(f_atoms, W_i_atom, p_ia, N_ATOMS, H, ATOM_F,
                                            nullptr, nullptr, 1);
    gemm_k<<<gemm_grid(N_BONDS, H), gthr>>>(f_bonds, W_i_bond, p_ib, N_BONDS, H, BOND_F,
                                            nullptr, nullptr, 1);
    cudaMemcpyAsync(p_ma, p_ia, sizeof(float) * (size_t)N_ATOMS * H, cudaMemcpyDeviceToDevice, 0);
    cudaMemcpyAsync(p_mb, p_ib, sizeof(float) * (size_t)N_BONDS * H, cudaMemcpyDeviceToDevice, 0);

    // 2) two message-passing steps
    for (int d = 0; d < 2; d++) {
        agg_update_k<<<(N_ATOMS * H4 + EB - 1) / EB, EB>>>(a2b, (const float4*)p_mb,
                                                           (float4*)p_ma);
        bond_tmp_k<<<(N_BONDS * H4 + EB - 1) / EB, EB>>>(b2a, b2revb, (const float4*)p_ma,
                                                         (const float4*)p_mb, (float4*)p_tmp);
        gemm_k<<<gemm_grid(N_BONDS, H), gthr>>>(p_tmp, d ? W_h_1 : W_h_0, p_mb,
                                                N_BONDS, H, H, p_ib, nullptr, 1);
    }

    // 3) final aggregation + concat + readout
    final_cat_k<<<(N_ATOMS * H4 + EB - 1) / EB, EB>>>(a2b, (const float4*)p_mb,
                                                      (const float4*)p_ma, (const float4*)p_ia,
                                                      (float4*)p_cat);
    gemm_k<<<gemm_grid(N_ATOMS, H), gthr>>>(p_cat, W_lr, p_lr, N_ATOMS, H, H3,
                                            nullptr, nullptr, 0);

    // 4) GRU prep
    msg_k<<<(N_ATOMS * H4 + EB - 1) / EB, EB>>>((const float4*)p_lr, (const float4*)gru_bias,
                                                (float4*)p_msg);
    h0_k<<<(NMOL * H + EB - 1) / EB, EB>>>(p_lr, p_h0);
    transpose_k<<<(H3 * H + EB - 1) / EB, EB>>>(Wih_f, p_wtihf);
    transpose_k<<<(H3 * H + EB - 1) / EB, EB>>>(Whh_f, p_wthhf);
    transpose_k<<<(H3 * H + EB - 1) / EB, EB>>>(Wih_b, p_wtihb);
    transpose_k<<<(H3 * H + EB - 1) / EB, EB>>>(Whh_b, p_wthhb);

    // gi = x @ Wih^T + bih for all timesteps
    gemm_k<<<gemm_grid(NMOL * APM, H3), gthr>>>(p_msg + H, p_wtihf, p_gif,
                                                NMOL * APM, H3, H, nullptr, bih_f, 0);
    gemm_k<<<gemm_grid(NMOL * APM, H3), gthr>>>(p_msg + H, p_wtihb, p_gib,
                                                NMOL * APM, H3, H, nullptr, bih_b, 0);

    // 5) 64 fused bidirectional GRU steps (4 mols/block -> 256 blocks)
    for (int s = 0; s < APM; s++)
        gru_step_k<<<dim3(NMOL / 4, 2), H>>>(s, p_gif, p_gib, p_wthhf, p_wthhb,
                                             bhh_f, bhh_b, p_h0, p_outf, p_outb);

    // 6) concat directions, output projection (plain FMA: post-GRU), mean
    gru_cat_k<<<((N_ATOMS - 1) * H24 + EB - 1) / EB, EB>>>((const float4*)p_outf,
                                                           (const float4*)p_outb,
                                                           (float4*)p_cat2);
    gemm_plain_k<<<gemm_grid(NMOL * APM, H), gthr>>>(p_cat2, W_o, p_ah,
                                                     NMOL * APM, H, 2 * H, b_o, 1);
    mean_k<<<(NMOL * H + EB - 1) / EB, EB>>>(p_ah, out);
}